// round 1
// baseline (speedup 1.0000x reference)
#include <cuda_runtime.h>

#define Nn 2
#define Cc 8
#define Hh 256
#define Ww 512
#define KK 9
#define PADW 4
#define BH 8
#define BW 64
#define TWX 16                 // threads along w, each covers 4 outputs
#define ROWS (BH + 8)          // 16
#define COLS (BW + 8)          // 72
#define NTHREADS (TWX * BH)    // 128

__global__ __launch_bounds__(NTHREADS)
void dfl_kernel(const float* __restrict__ x,
                const float* __restrict__ filt,
                const float* __restrict__ bias,
                float* __restrict__ out)
{
    __shared__ float sx[Cc][ROWS][COLS];   // 36,864 B

    const int n  = blockIdx.z;
    const int h0 = blockIdx.y * BH;
    const int w0 = blockIdx.x * BW;
    const int tid = threadIdx.y * TWX + threadIdx.x;

    // ---- fill shared x tile (zero-padded halo) ----
    const float* xn = x + (size_t)n * Cc * Hh * Ww;
    // Cc*ROWS*18 float4 groups = 2304; 128 threads -> 18 groups each
    #pragma unroll
    for (int g = tid; g < Cc * ROWS * 18; g += NTHREADS) {
        int q  = g % 18;
        int rc = g / 18;
        int r  = rc % ROWS;
        int c  = rc / ROWS;
        int gh = h0 - PADW + r;
        int gw = w0 - PADW + q * 4;
        float4 v = make_float4(0.f, 0.f, 0.f, 0.f);
        if (gh >= 0 && gh < Hh) {
            const float* row = xn + ((size_t)c * Hh + gh) * Ww;
            if (gw >= 0 && gw + 3 < Ww) {
                v = *reinterpret_cast<const float4*>(row + gw);
            } else {
                float t0 = (gw + 0 >= 0 && gw + 0 < Ww) ? row[gw + 0] : 0.f;
                float t1 = (gw + 1 >= 0 && gw + 1 < Ww) ? row[gw + 1] : 0.f;
                float t2 = (gw + 2 >= 0 && gw + 2 < Ww) ? row[gw + 2] : 0.f;
                float t3 = (gw + 3 >= 0 && gw + 3 < Ww) ? row[gw + 3] : 0.f;
                v = make_float4(t0, t1, t2, t3);
            }
        }
        *reinterpret_cast<float4*>(&sx[c][r][q * 4]) = v;   // 16B aligned: 72*4 row stride
    }
    __syncthreads();

    // ---- compute: each thread -> 4 w outputs x 8 channels at one h ----
    const int hl = threadIdx.y;          // 0..7
    const int h  = h0 + hl;
    const int wl = threadIdx.x * 4;      // local output col 0..60
    const int w  = w0 + wl;

    float4 acc[Cc];
    {
        float4 b = *reinterpret_cast<const float4*>(bias + ((size_t)n * Hh + h) * Ww + w);
        #pragma unroll
        for (int c = 0; c < Cc; c++) acc[c] = b;
    }

    const float* fbase = filt + ((size_t)n * (KK * KK) * Hh + h) * Ww + w;
    const size_t tap_stride = (size_t)Hh * Ww;

    for (int i = 0; i < KK; i++) {
        // filter taps for this i-row: shared across all 8 channels
        float4 f[KK];
        #pragma unroll
        for (int j = 0; j < KK; j++)
            f[j] = *reinterpret_cast<const float4*>(fbase + (size_t)(i * KK + j) * tap_stride);

        #pragma unroll
        for (int c = 0; c < Cc; c++) {
            // 12-float window: output col wl maps to tile col wl (halo already offset)
            const float* sp = &sx[c][hl + i][wl];
            float4 x0 = *reinterpret_cast<const float4*>(sp);
            float4 x1 = *reinterpret_cast<const float4*>(sp + 4);
            float4 x2 = *reinterpret_cast<const float4*>(sp + 8);
            float xw[12] = { x0.x, x0.y, x0.z, x0.w,
                             x1.x, x1.y, x1.z, x1.w,
                             x2.x, x2.y, x2.z, x2.w };
            #pragma unroll
            for (int j = 0; j < KK; j++) {
                acc[c].x = fmaf(xw[j + 0], f[j].x, acc[c].x);
                acc[c].y = fmaf(xw[j + 1], f[j].y, acc[c].y);
                acc[c].z = fmaf(xw[j + 2], f[j].z, acc[c].z);
                acc[c].w = fmaf(xw[j + 3], f[j].w, acc[c].w);
            }
        }
    }

    // ---- store ----
    float* obase = out + (((size_t)n * Cc) * Hh + h) * Ww + w;
    #pragma unroll
    for (int c = 0; c < Cc; c++)
        *reinterpret_cast<float4*>(obase + (size_t)c * Hh * Ww) = acc[c];
}

extern "C" void kernel_launch(void* const* d_in, const int* in_sizes, int n_in,
                              void* d_out, int out_size)
{
    const float* x    = (const float*)d_in[0];   // x_in  (2,8,256,512)
    const float* filt = (const float*)d_in[1];   // filters (2,81,256,512)
    const float* bias = (const float*)d_in[2];   // filters_biases (2,1,256,512)
    float* out = (float*)d_out;

    dim3 grid(Ww / BW, Hh / BH, Nn);   // (8, 32, 2)
    dim3 block(TWX, BH, 1);            // (16, 8)
    dfl_kernel<<<grid, block>>>(x, filt, bias, out);
}

// round 2
// speedup vs baseline: 1.1839x; 1.1839x over previous
#include <cuda_runtime.h>

#define Nn 2
#define Cc 8
#define Hh 256
#define Ww 512
#define KK 9
#define PADW 4
#define BH 8
#define BW 32
#define TWX 16                 // threads along w, each covers 2 outputs
#define ROWS (BH + 8)          // 16
#define COLS (BW + 8)          // 40
#define NTHREADS (TWX * BH)    // 128

__global__ __launch_bounds__(NTHREADS, 6)
void dfl_kernel(const float* __restrict__ x,
                const float* __restrict__ filt,
                const float* __restrict__ bias,
                float* __restrict__ out)
{
    __shared__ float sx[Cc][ROWS][COLS];   // 20,480 B

    const int n  = blockIdx.z;
    const int h0 = blockIdx.y * BH;
    const int w0 = blockIdx.x * BW;
    const int tid = threadIdx.y * TWX + threadIdx.x;

    // ---- fill shared x tile (zero-padded halo) ----
    // Cc*ROWS*10 float4 groups = 1280; 128 threads -> 10 groups each
    const float* xn = x + (size_t)n * Cc * Hh * Ww;
    #pragma unroll
    for (int g = tid; g < Cc * ROWS * 10; g += NTHREADS) {
        int q  = g % 10;
        int rc = g / 10;
        int r  = rc % ROWS;
        int c  = rc / ROWS;
        int gh = h0 - PADW + r;
        int gw = w0 - PADW + q * 4;
        float4 v = make_float4(0.f, 0.f, 0.f, 0.f);
        if (gh >= 0 && gh < Hh) {
            const float* row = xn + ((size_t)c * Hh + gh) * Ww;
            if (gw >= 0 && gw + 3 < Ww) {
                v = *reinterpret_cast<const float4*>(row + gw);
            } else {
                float t0 = (gw + 0 >= 0 && gw + 0 < Ww) ? row[gw + 0] : 0.f;
                float t1 = (gw + 1 >= 0 && gw + 1 < Ww) ? row[gw + 1] : 0.f;
                float t2 = (gw + 2 >= 0 && gw + 2 < Ww) ? row[gw + 2] : 0.f;
                float t3 = (gw + 3 >= 0 && gw + 3 < Ww) ? row[gw + 3] : 0.f;
                v = make_float4(t0, t1, t2, t3);
            }
        }
        // COLS*4 = 160B row stride -> q*16 offsets stay 16B aligned
        *reinterpret_cast<float4*>(&sx[c][r][q * 4]) = v;
    }
    __syncthreads();

    // ---- compute: each thread -> 2 w outputs x 8 channels at one h ----
    const int hl = threadIdx.y;          // 0..7
    const int h  = h0 + hl;
    const int wl = threadIdx.x * 2;      // local output col (even)
    const int w  = w0 + wl;

    float2 acc[Cc];
    {
        float2 b = *reinterpret_cast<const float2*>(bias + ((size_t)n * Hh + h) * Ww + w);
        #pragma unroll
        for (int c = 0; c < Cc; c++) acc[c] = b;
    }

    const float* fbase = filt + ((size_t)n * (KK * KK) * Hh + h) * Ww + w;
    const size_t tap_stride = (size_t)Hh * Ww;

    for (int i = 0; i < KK; i++) {
        // 9 independent filter-tap loads, shared across all 8 channels
        float2 f[KK];
        #pragma unroll
        for (int j = 0; j < KK; j++)
            f[j] = *reinterpret_cast<const float2*>(fbase + (size_t)(i * KK + j) * tap_stride);

        #pragma unroll
        for (int c = 0; c < Cc; c++) {
            // 10-float window (8B-aligned): 5 x LDS.64
            const float* sp = &sx[c][hl + i][wl];
            float2 x0 = *reinterpret_cast<const float2*>(sp);
            float2 x1 = *reinterpret_cast<const float2*>(sp + 2);
            float2 x2 = *reinterpret_cast<const float2*>(sp + 4);
            float2 x3 = *reinterpret_cast<const float2*>(sp + 6);
            float2 x4 = *reinterpret_cast<const float2*>(sp + 8);
            float xw[10] = { x0.x, x0.y, x1.x, x1.y, x2.x,
                             x2.y, x3.x, x3.y, x4.x, x4.y };
            #pragma unroll
            for (int j = 0; j < KK; j++) {
                acc[c].x = fmaf(xw[j + 0], f[j].x, acc[c].x);
                acc[c].y = fmaf(xw[j + 1], f[j].y, acc[c].y);
            }
        }
    }

    // ---- store ----
    float* obase = out + (((size_t)n * Cc) * Hh + h) * Ww + w;
    #pragma unroll
    for (int c = 0; c < Cc; c++)
        *reinterpret_cast<float2*>(obase + (size_t)c * Hh * Ww) = acc[c];
}

extern "C" void kernel_launch(void* const* d_in, const int* in_sizes, int n_in,
                              void* d_out, int out_size)
{
    const float* x    = (const float*)d_in[0];   // x_in  (2,8,256,512)
    const float* filt = (const float*)d_in[1];   // filters (2,81,256,512)
    const float* bias = (const float*)d_in[2];   // filters_biases (2,1,256,512)
    float* out = (float*)d_out;

    dim3 grid(Ww / BW, Hh / BH, Nn);   // (16, 32, 2) = 1024 CTAs
    dim3 block(TWX, BH, 1);            // (16, 8)
    dfl_kernel<<<grid, block>>>(x, filt, bias, out);
}